// round 3
// baseline (speedup 1.0000x reference)
#include <cuda_runtime.h>
#include <math.h>

#define BB 32
#define TT 100
#define NN 150
#define CHN 32
#define HID1 512
#define RHID2 150
#define DIN (NN*CHN)        // 4800
#define G1 (3*HID1)         // 1536
#define G2 (3*RHID2)        // 450
#define ROWS (BB*TT)        // 3200
#define NTOT (BB*NN*TT)     // 480000
#define TOPK 10
#define DECS 152            // padded stride for dec / W_fc (16B-aligned rows)

// ---------------- scratch (device globals; no allocation allowed) ----------------
__device__ __align__(256) float g_Mt[NN*NN];
__device__ __align__(256) float g_xf[NTOT];              // x in torch (b,n,t) flat layout
__device__ __align__(256) float g_xt[(size_t)ROWS*DIN];
__device__ __align__(256) float g_xi1[(size_t)ROWS*G1];
__device__ __align__(256) float g_h[2*BB*HID1];
__device__ __align__(256) float g_hrep[(size_t)ROWS*HID1];
__device__ __align__(256) float g_xi2[(size_t)ROWS*G2];
__device__ __align__(256) float g_dec[(size_t)ROWS*DECS];
__device__ __align__(256) float g_Wh2T[RHID2*G2];
__device__ __align__(256) float g_WfcP[NN*DECS];

// ---------------- graph construction: cosine knn -> normalized dense M^T ----------------
__global__ void k_graph(const float* __restrict__ emb, float* __restrict__ Mt) {
    __shared__ float Wn[NN][CHN];
    __shared__ float rowbuf[8][NN+2];
    __shared__ int   eidx[NN*TOPK];
    __shared__ float eval_[NN*TOPK];
    __shared__ float deg[NN];
    __shared__ float dinv[NN];
    int tid = threadIdx.x;
    for (int i = tid; i < NN; i += blockDim.x) {
        float s = 0.f;
        for (int c = 0; c < CHN; c++) { float v = emb[i*CHN+c]; s += v*v; }
        float nrm = fmaxf(sqrtf(s), 1e-8f);
        float inv = 1.f/nrm;
        for (int c = 0; c < CHN; c++) Wn[i][c] = emb[i*CHN+c]*inv;
    }
    for (int i = tid; i < NN; i += blockDim.x) deg[i] = 0.f;
    __syncthreads();
    int w = tid >> 5, l = tid & 31;
    for (int i = w; i < NN; i += 8) {
        for (int j = l; j < NN; j += 32) {
            float s = 0.f;
            #pragma unroll
            for (int c = 0; c < CHN; c++) s += Wn[i][c]*Wn[j][c];
            if (j == i) s = 0.f;
            rowbuf[w][j] = fmaxf(s, 0.f);
        }
        __syncwarp();
        for (int rep = 0; rep < TOPK; rep++) {
            float bv = -2.f; int bi = 1<<30;
            for (int j = l; j < NN; j += 32) {
                float v = rowbuf[w][j];
                if (v > bv) { bv = v; bi = j; }   // ascending j => lowest index on tie
            }
            for (int off = 16; off; off >>= 1) {
                float ov = __shfl_down_sync(0xffffffffu, bv, off);
                int   oi = __shfl_down_sync(0xffffffffu, bi, off);
                if (ov > bv || (ov == bv && oi < bi)) { bv = ov; bi = oi; }
            }
            bv = __shfl_sync(0xffffffffu, bv, 0);
            bi = __shfl_sync(0xffffffffu, bi, 0);
            if (l == 0) {
                eidx[i*TOPK+rep] = bi;
                eval_[i*TOPK+rep] = bv;
                rowbuf[w][bi] = -1.f;
            }
            __syncwarp();
        }
    }
    __syncthreads();
    for (int e = tid; e < NN*TOPK; e += blockDim.x)
        atomicAdd(&deg[eidx[e]], eval_[e]);
    __syncthreads();
    for (int i = tid; i < NN; i += blockDim.x)
        dinv[i] = deg[i] > 0.f ? 1.f/sqrtf(deg[i]) : 0.f;
    for (int i = tid; i < NN*NN; i += blockDim.x) Mt[i] = 0.f;
    __syncthreads();
    for (int e = tid; e < NN*TOPK; e += blockDim.x) {
        int src = e / TOPK;
        int dst = eidx[e];
        Mt[src*NN + dst] = dinv[src]*eval_[e]*dinv[dst];
    }
}

// ---------------- permute window [B,T,N] -> x_flat[(b*N+n)*T + t] ----------------
__global__ void k_perm(const float* __restrict__ window, float* __restrict__ xf) {
    int i = blockIdx.x*blockDim.x + threadIdx.x;
    if (i >= NTOT) return;
    int t  = i % TT;
    int bn = i / TT;
    int n  = bn % NN;
    int b  = bn / NN;
    xf[i] = window[(b*TT + t)*NN + n];
}

// ---------------- ARMA conv (raw-flat-index graph!) + gelu + emb -> xt ----------------
// The reference's edges use t-major flat indices while features are (b,n)-major;
// net effect: agg[f] = sum_i M[i][f%150] * xf[(f/150)*150 + i].  Each block handles
// one contiguous 150-slice of xf, then scatters outputs to GRU layout via decoding
// f = (b_x*150 + n_x)*100 + t_x.
__global__ void k_arma(const float* __restrict__ xf, const float* __restrict__ emb,
                       const float* __restrict__ w_init, const float* __restrict__ w_root,
                       const float* __restrict__ arma_b,
                       const float* __restrict__ Mt, float* __restrict__ xt) {
    __shared__ float xs[NN];
    __shared__ float s[NN];
    int blk = blockIdx.x;                 // 0..3199
    int base = blk*NN;
    int tid = threadIdx.x;
    for (int i = tid; i < NN; i += blockDim.x) xs[i] = xf[base + i];
    __syncthreads();
    for (int n = tid; n < NN; n += blockDim.x) {
        float acc = 0.f;
        #pragma unroll 5
        for (int m = 0; m < NN; m++) acc += Mt[m*NN+n]*xs[m];   // coalesced over n
        s[n] = acc;
    }
    __syncthreads();
    for (int i = tid; i < DIN; i += blockDim.x) {
        int n = i >> 5, c = i & 31;
        int f = base + n;                 // raw flat node index (b,n)-major
        int bx  = f / (NN*TT);
        int rem = f - bx*(NN*TT);
        int nx  = rem / TT;
        int tx2 = rem - nx*TT;
        float v = s[n]*w_init[c] + xs[n]*w_root[c] + arma_b[c];
        float g = 0.5f*v*(1.f + erff(v*0.70710678118654752f));
        xt[((size_t)(bx*TT + tx2))*DIN + nx*CHN + c] = g + emb[nx*CHN + c];
    }
}

// ---------------- generic NT GEMM: C[M,N] = A[M,K] @ B[N,K]^T + bias ----------------
// lda/ldb must keep every row 16B-aligned.
__global__ void gemm_nt_bias(const float* __restrict__ A, const float* __restrict__ Bm,
                             const float* __restrict__ bias, float* __restrict__ C,
                             int M, int N, int K, int lda, int ldb, int ldc) {
    __shared__ float As[16][132];
    __shared__ float Bs[16][132];
    const int tid = threadIdx.x;
    const int tx = tid & 15, ty = tid >> 4;
    const int bm = blockIdx.y * 128, bn = blockIdx.x * 128;
    float acc[8][8];
    #pragma unroll
    for (int i = 0; i < 8; i++)
        #pragma unroll
        for (int j = 0; j < 8; j++) acc[i][j] = 0.f;
    for (int k0 = 0; k0 < K; k0 += 16) {
        #pragma unroll
        for (int q = 0; q < 2; q++) {
            int idx = tid + q*256;
            int row = idx >> 2;
            int c4  = (idx & 3) << 2;
            int gk = k0 + c4;
            float4 va = make_float4(0.f,0.f,0.f,0.f);
            float4 vb = make_float4(0.f,0.f,0.f,0.f);
            int ga = bm + row, gb = bn + row;
            if (ga < M && gk < K) {
                const float* p = A + (size_t)ga*lda;
                if (gk + 3 < K) va = *(const float4*)(p + gk);
                else {
                    va.x = p[gk];
                    if (gk+1 < K) va.y = p[gk+1];
                    if (gk+2 < K) va.z = p[gk+2];
                }
            }
            if (gb < N && gk < K) {
                const float* p = Bm + (size_t)gb*ldb;
                if (gk + 3 < K) vb = *(const float4*)(p + gk);
                else {
                    vb.x = p[gk];
                    if (gk+1 < K) vb.y = p[gk+1];
                    if (gk+2 < K) vb.z = p[gk+2];
                }
            }
            As[c4+0][row]=va.x; As[c4+1][row]=va.y; As[c4+2][row]=va.z; As[c4+3][row]=va.w;
            Bs[c4+0][row]=vb.x; Bs[c4+1][row]=vb.y; Bs[c4+2][row]=vb.z; Bs[c4+3][row]=vb.w;
        }
        __syncthreads();
        #pragma unroll
        for (int kk = 0; kk < 16; kk++) {
            float4 a0 = *(const float4*)&As[kk][ty*4];
            float4 a1 = *(const float4*)&As[kk][64 + ty*4];
            float4 b0 = *(const float4*)&Bs[kk][tx*4];
            float4 b1 = *(const float4*)&Bs[kk][64 + tx*4];
            float a[8] = {a0.x,a0.y,a0.z,a0.w,a1.x,a1.y,a1.z,a1.w};
            float b[8] = {b0.x,b0.y,b0.z,b0.w,b1.x,b1.y,b1.z,b1.w};
            #pragma unroll
            for (int i = 0; i < 8; i++)
                #pragma unroll
                for (int j = 0; j < 8; j++) acc[i][j] += a[i]*b[j];
        }
        __syncthreads();
    }
    #pragma unroll
    for (int i = 0; i < 8; i++) {
        int gm = bm + ((i < 4) ? ty*4+i : 64+ty*4+(i-4));
        if (gm >= M) continue;
        #pragma unroll
        for (int j = 0; j < 8; j++) {
            int gn = bn + ((j < 4) ? tx*4+j : 64+tx*4+(j-4));
            if (gn < N) C[(size_t)gm*ldc + gn] = acc[i][j] + bias[gn];
        }
    }
}

// ---------------- GRU1 single step (launched T times) ----------------
__global__ void gru1_step(const float* __restrict__ xi1, const float* __restrict__ Wh1,
                          const float* __restrict__ bh1,
                          const float* __restrict__ hin, float* __restrict__ hout, int t) {
    extern __shared__ float hs[];     // [32][516]
    const int STR = 516;
    int tid = threadIdx.x;
    for (int i = tid; i < BB*(HID1/4); i += blockDim.x) {
        int b  = i >> 7;
        int k4 = (i & 127) << 2;
        float4 v = *(const float4*)(hin + b*HID1 + k4);
        *(float4*)&hs[b*STR + k4] = v;
    }
    __syncthreads();
    int w = tid >> 5, l = tid & 31;
    int j = blockIdx.x*4 + w;
    const float* wr = Wh1 + (size_t)j*HID1;
    const float* wz = wr + (size_t)HID1*HID1;
    const float* wn = wz + (size_t)HID1*HID1;
    const float* hb = hs + l*STR;
    float ar = 0.f, az = 0.f, an = 0.f;
    #pragma unroll 8
    for (int k = 0; k < HID1; k += 4) {
        float4 h4 = *(const float4*)(hb + k);
        float4 r4 = *(const float4*)(wr + k);
        float4 z4 = *(const float4*)(wz + k);
        float4 n4 = *(const float4*)(wn + k);
        ar += r4.x*h4.x + r4.y*h4.y + r4.z*h4.z + r4.w*h4.w;
        az += z4.x*h4.x + z4.y*h4.y + z4.z*h4.z + z4.w*h4.w;
        an += n4.x*h4.x + n4.y*h4.y + n4.z*h4.z + n4.w*h4.w;
    }
    int row = l*TT + t;
    const float* xrow = xi1 + (size_t)row*G1;
    float gr = ar + bh1[j];
    float gz = az + bh1[HID1+j];
    float gn = an + bh1[2*HID1+j];
    float r = 1.f/(1.f + expf(-(xrow[j] + gr)));
    float z = 1.f/(1.f + expf(-(xrow[HID1+j] + gz)));
    float n = tanhf(xrow[2*HID1+j] + r*gn);
    hout[l*HID1 + j] = (1.f - z)*n + z*hs[l*STR + j];
}

// ---------------- repeat_interleave(T) then view(B,T,HID) ----------------
__global__ void k_hrep(const float* __restrict__ hend, float* __restrict__ hrep) {
    int i = blockIdx.x*blockDim.x + threadIdx.x;
    if (i >= ROWS*HID1) return;
    int row = i >> 9;
    int d = i & 511;
    int b = row / TT, t = row - b*TT;
    hrep[i] = hend[b*HID1 + (t*HID1 + d)/TT];
}

__global__ void k_transpose450(const float* __restrict__ Wh2, float* __restrict__ Wh2T) {
    int i = blockIdx.x*blockDim.x + threadIdx.x;
    if (i >= G2*RHID2) return;
    int r = i / RHID2, c = i - r*RHID2;
    Wh2T[c*G2 + r] = Wh2[i];
}

__global__ void k_padWfc(const float* __restrict__ Wfc, float* __restrict__ WfcP) {
    int i = blockIdx.x*blockDim.x + threadIdx.x;
    if (i >= NN*DECS) return;
    int r = i / DECS, c = i - r*DECS;
    WfcP[i] = (c < RHID2) ? Wfc[r*RHID2 + c] : 0.f;
}

__global__ void k_zero(float* __restrict__ p, int n) {
    int i = blockIdx.x*blockDim.x + threadIdx.x;
    if (i < n) p[i] = 0.f;
}

// ---------------- GRU2: all T steps in one kernel, one block per batch ----------------
__global__ void k_gru2(const float* __restrict__ xi2, const float* __restrict__ Wh2T,
                       const float* __restrict__ bh2, float* __restrict__ dec) {
    __shared__ float h[RHID2];
    int b = blockIdx.x, tid = threadIdx.x;
    for (int i = tid; i < RHID2; i += blockDim.x) h[i] = 0.f;
    __syncthreads();
    for (int t = 0; t < TT; t++) {
        float ar = 0.f, az = 0.f, an = 0.f;
        if (tid < RHID2) {
            #pragma unroll 5
            for (int k = 0; k < RHID2; k++) {
                float hk = h[k];
                const float* wrow = Wh2T + k*G2;
                ar += wrow[tid]          * hk;
                az += wrow[RHID2 + tid]  * hk;
                an += wrow[2*RHID2 + tid]* hk;
            }
        }
        __syncthreads();
        if (tid < RHID2) {
            int row = b*TT + t;
            const float* xrow = xi2 + (size_t)row*G2;
            float r = 1.f/(1.f + expf(-(xrow[tid] + ar + bh2[tid])));
            float z = 1.f/(1.f + expf(-(xrow[RHID2+tid] + az + bh2[RHID2+tid])));
            float n = tanhf(xrow[2*RHID2+tid] + r*(an + bh2[2*RHID2+tid]));
            float hn = (1.f - z)*n + z*h[tid];
            h[tid] = hn;
            dec[(size_t)row*DECS + tid] = hn;
        }
        __syncthreads();
    }
}

// ---------------- launch ----------------
extern "C" void kernel_launch(void* const* d_in, const int* in_sizes, int n_in,
                              void* d_out, int out_size) {
    const float* window = (const float*)d_in[0];
    const float* emb    = (const float*)d_in[1];
    const float* w_init = (const float*)d_in[2];
    const float* w_root = (const float*)d_in[3];
    const float* arma_b = (const float*)d_in[4];
    const float* Wi1    = (const float*)d_in[5];
    const float* Wh1    = (const float*)d_in[6];
    const float* bi1    = (const float*)d_in[7];
    const float* bh1    = (const float*)d_in[8];
    const float* Wi2    = (const float*)d_in[9];
    const float* Wh2    = (const float*)d_in[10];
    const float* bi2    = (const float*)d_in[11];
    const float* bh2    = (const float*)d_in[12];
    const float* W_fc   = (const float*)d_in[13];
    const float* b_fc   = (const float*)d_in[14];
    float* out = (float*)d_out;

    float *Mt, *xf, *xt, *xi1, *hbase, *hrep, *xi2, *dec, *Wh2T, *WfcP;
    cudaGetSymbolAddress((void**)&Mt,    g_Mt);
    cudaGetSymbolAddress((void**)&xf,    g_xf);
    cudaGetSymbolAddress((void**)&xt,    g_xt);
    cudaGetSymbolAddress((void**)&xi1,   g_xi1);
    cudaGetSymbolAddress((void**)&hbase, g_h);
    cudaGetSymbolAddress((void**)&hrep,  g_hrep);
    cudaGetSymbolAddress((void**)&xi2,   g_xi2);
    cudaGetSymbolAddress((void**)&dec,   g_dec);
    cudaGetSymbolAddress((void**)&Wh2T,  g_Wh2T);
    cudaGetSymbolAddress((void**)&WfcP,  g_WfcP);
    float* hb[2] = { hbase, hbase + BB*HID1 };

    const int smem_gru1 = BB*516*4;   // 66048 B
    cudaFuncSetAttribute(gru1_step, cudaFuncAttributeMaxDynamicSharedMemorySize, smem_gru1);

    k_graph<<<1, 256>>>(emb, Mt);
    k_perm<<<(NTOT + 255)/256, 256>>>(window, xf);
    k_arma<<<ROWS, 160>>>(xf, emb, w_init, w_root, arma_b, Mt, xt);

    // big GEMM: xi1 = xt @ Wi1^T + bi1   [3200,4800]x[4800,1536]
    gemm_nt_bias<<<dim3(G1/128, (ROWS+127)/128), 256>>>(xt, Wi1, bi1, xi1,
                                                        ROWS, G1, DIN, DIN, DIN, G1);

    k_zero<<<(BB*HID1 + 255)/256, 256>>>(hb[0], BB*HID1);
    for (int t = 0; t < TT; t++)
        gru1_step<<<128, 128, smem_gru1>>>(xi1, Wh1, bh1, hb[t & 1], hb[(t+1) & 1], t);
    // final h in hb[0]

    k_hrep<<<(ROWS*HID1 + 255)/256, 256>>>(hb[0], hrep);
    gemm_nt_bias<<<dim3((G2+127)/128, (ROWS+127)/128), 256>>>(hrep, Wi2, bi2, xi2,
                                                              ROWS, G2, HID1, HID1, HID1, G2);

    k_transpose450<<<(G2*RHID2 + 255)/256, 256>>>(Wh2, Wh2T);
    k_gru2<<<BB, 160>>>(xi2, Wh2T, bh2, dec);

    k_padWfc<<<(NN*DECS + 255)/256, 256>>>(W_fc, WfcP);
    gemm_nt_bias<<<dim3((NN+127)/128, (ROWS+127)/128), 256>>>(dec, WfcP, b_fc, out,
                                                              ROWS, NN, RHID2, DECS, DECS, NN);
}

// round 5
// speedup vs baseline: 1.1837x; 1.1837x over previous
#include <cuda_runtime.h>
#include <cuda_bf16.h>
#include <math.h>
#include <stdint.h>

#define BB 32
#define TT 100
#define NN 150
#define CHN 32
#define HID1 512
#define RHID2 150
#define DIN (NN*CHN)        // 4800
#define G1 (3*HID1)         // 1536
#define G2 (3*RHID2)        // 450
#define ROWS (BB*TT)        // 3200
#define NTOT (BB*NN*TT)     // 480000
#define TOPK 10
#define DECS 152

// ---------------- scratch ----------------
__device__ __align__(256) float g_Mt[NN*NN];
__device__ __align__(256) float g_xf[NTOT];
__device__ __align__(256) __nv_bfloat16 g_Ahi[(size_t)ROWS*DIN];
__device__ __align__(256) __nv_bfloat16 g_Alo[(size_t)ROWS*DIN];
__device__ __align__(256) __nv_bfloat16 g_Bhi[(size_t)G1*DIN];
__device__ __align__(256) __nv_bfloat16 g_Blo[(size_t)G1*DIN];
__device__ __align__(256) float g_xi1[(size_t)ROWS*G1];
__device__ __align__(256) float g_h[2*BB*HID1];
__device__ __align__(256) float g_hrep[(size_t)ROWS*HID1];
__device__ __align__(256) float g_xi2[(size_t)ROWS*G2];
__device__ __align__(256) float g_dec[(size_t)ROWS*DECS];
__device__ __align__(256) float g_Wh2T[RHID2*G2];
__device__ __align__(256) float g_WfcP[NN*DECS];
__device__ volatile int g_flags[128];

__device__ __forceinline__ uint32_t smem_u32(const void* p) {
    uint32_t a;
    asm("{ .reg .u64 t; cvta.to.shared.u64 t, %1; cvt.u32.u64 %0, t; }" : "=r"(a) : "l"(p));
    return a;
}
__device__ __forceinline__ void ldsm_x4(uint32_t* r, uint32_t addr) {
    asm volatile("ldmatrix.sync.aligned.m8n8.x4.shared.b16 {%0,%1,%2,%3}, [%4];"
        : "=r"(r[0]), "=r"(r[1]), "=r"(r[2]), "=r"(r[3]) : "r"(addr));
}
__device__ __forceinline__ void mma16816(float* c, const uint32_t* a, const uint32_t* b) {
    asm volatile("mma.sync.aligned.m16n8k16.row.col.f32.bf16.bf16.f32 "
        "{%0,%1,%2,%3}, {%4,%5,%6,%7}, {%8,%9}, {%0,%1,%2,%3};"
        : "+f"(c[0]), "+f"(c[1]), "+f"(c[2]), "+f"(c[3])
        : "r"(a[0]), "r"(a[1]), "r"(a[2]), "r"(a[3]), "r"(b[0]), "r"(b[1]));
}
__device__ __forceinline__ uint32_t sw128(uint32_t off) {
    return off ^ ((off >> 3) & 0x70);
}

// ---------------- graph construction ----------------
__global__ void k_graph(const float* __restrict__ emb, float* __restrict__ Mt) {
    __shared__ float Wn[NN][CHN];
    __shared__ float rowbuf[8][NN+2];
    __shared__ int   eidx[NN*TOPK];
    __shared__ float eval_[NN*TOPK];
    __shared__ float deg[NN];
    __shared__ float dinv[NN];
    int tid = threadIdx.x;
    for (int i = tid; i < NN; i += blockDim.x) {
        float s = 0.f;
        for (int c = 0; c < CHN; c++) { float v = emb[i*CHN+c]; s += v*v; }
        float inv = 1.f/fmaxf(sqrtf(s), 1e-8f);
        for (int c = 0; c < CHN; c++) Wn[i][c] = emb[i*CHN+c]*inv;
    }
    for (int i = tid; i < NN; i += blockDim.x) deg[i] = 0.f;
    __syncthreads();
    int w = tid >> 5, l = tid & 31;
    for (int i = w; i < NN; i += 8) {
        for (int j = l; j < NN; j += 32) {
            float s = 0.f;
            #pragma unroll
            for (int c = 0; c < CHN; c++) s += Wn[i][c]*Wn[j][c];
            if (j == i) s = 0.f;
            rowbuf[w][j] = fmaxf(s, 0.f);
        }
        __syncwarp();
        for (int rep = 0; rep < TOPK; rep++) {
            float bv = -2.f; int bi = 1<<30;
            for (int j = l; j < NN; j += 32) {
                float v = rowbuf[w][j];
                if (v > bv) { bv = v; bi = j; }
            }
            for (int off = 16; off; off >>= 1) {
                float ov = __shfl_down_sync(0xffffffffu, bv, off);
                int   oi = __shfl_down_sync(0xffffffffu, bi, off);
                if (ov > bv || (ov == bv && oi < bi)) { bv = ov; bi = oi; }
            }
            bv = __shfl_sync(0xffffffffu, bv, 0);
            bi = __shfl_sync(0xffffffffu, bi, 0);
            if (l == 0) {
                eidx[i*TOPK+rep] = bi;
                eval_[i*TOPK+rep] = bv;
                rowbuf[w][bi] = -1.f;
            }
            __syncwarp();
        }
    }
    __syncthreads();
    for (int e = tid; e < NN*TOPK; e += blockDim.x)
        atomicAdd(&deg[eidx[e]], eval_[e]);
    __syncthreads();
    for (int i = tid; i < NN; i += blockDim.x)
        dinv[i] = deg[i] > 0.f ? 1.f/sqrtf(deg[i]) : 0.f;
    for (int i = tid; i < NN*NN; i += blockDim.x) Mt[i] = 0.f;
    __syncthreads();
    for (int e = tid; e < NN*TOPK; e += blockDim.x) {
        int src = e / TOPK;
        int dst = eidx[e];
        Mt[src*NN + dst] = dinv[src]*eval_[e]*dinv[dst];
    }
}

// ---------------- permute window [B,T,N] -> x_flat[(b*N+n)*T + t] ----------------
__global__ void k_perm(const float* __restrict__ window, float* __restrict__ xf) {
    int i = blockIdx.x*blockDim.x + threadIdx.x;
    if (i >= NTOT) return;
    int t  = i % TT;
    int bn = i / TT;
    int n  = bn % NN;
    int b  = bn / NN;
    xf[i] = window[(b*TT + t)*NN + n];
}

// ---------------- ARMA conv (raw-flat graph) + gelu + emb -> bf16 hi/lo ----------------
__global__ void k_arma(const float* __restrict__ xf, const float* __restrict__ emb,
                       const float* __restrict__ w_init, const float* __restrict__ w_root,
                       const float* __restrict__ arma_b, const float* __restrict__ Mt,
                       __nv_bfloat16* __restrict__ Ahi, __nv_bfloat16* __restrict__ Alo) {
    __shared__ float xs[NN];
    __shared__ float s[NN];
    int blk = blockIdx.x;
    int base = blk*NN;
    int tid = threadIdx.x;
    for (int i = tid; i < NN; i += blockDim.x) xs[i] = xf[base + i];
    __syncthreads();
    for (int n = tid; n < NN; n += blockDim.x) {
        float acc = 0.f;
        #pragma unroll 5
        for (int m = 0; m < NN; m++) acc += Mt[m*NN+n]*xs[m];
        s[n] = acc;
    }
    __syncthreads();
    for (int i = tid; i < DIN; i += blockDim.x) {
        int n = i >> 5, c = i & 31;
        int f = base + n;
        int bx  = f / (NN*TT);
        int rem = f - bx*(NN*TT);
        int nx  = rem / TT;
        int tx2 = rem - nx*TT;
        float v = s[n]*w_init[c] + xs[n]*w_root[c] + arma_b[c];
        float g = 0.5f*v*(1.f + erff(v*0.70710678118654752f));
        float val = g + emb[nx*CHN + c];
        __nv_bfloat16 hi = __float2bfloat16(val);
        float lo = val - __bfloat162float(hi);
        size_t idx = ((size_t)(bx*TT + tx2))*DIN + nx*CHN + c;
        Ahi[idx] = hi;
        Alo[idx] = __float2bfloat16(lo);
    }
}

// ---------------- Wi1 fp32 -> bf16 hi/lo split ----------------
__global__ void k_convW(const float* __restrict__ Wi1,
                        __nv_bfloat16* __restrict__ Bhi, __nv_bfloat16* __restrict__ Blo) {
    size_t i = (size_t)blockIdx.x*blockDim.x + threadIdx.x;
    if (i >= (size_t)G1*DIN) return;
    float v = Wi1[i];
    __nv_bfloat16 hi = __float2bfloat16(v);
    Bhi[i] = hi;
    Blo[i] = __float2bfloat16(v - __bfloat162float(hi));
}

// ---------------- mma.sync bf16-split GEMM: xi1 = A@B^T + bias ----------------
// M=3200, N=1536, K=4800. Block 128x128, 8 warps (warp tile 32x64), K-chunk 64.
// 3 passes per chunk: hi*hi, hi*lo, lo*hi (fp32 accumulate in registers).
__global__ void __launch_bounds__(256) gemm_mma(
    const __nv_bfloat16* __restrict__ Ahi, const __nv_bfloat16* __restrict__ Alo,
    const __nv_bfloat16* __restrict__ Bhi, const __nv_bfloat16* __restrict__ Blo,
    const float* __restrict__ bias, float* __restrict__ C) {
    extern __shared__ char dsm[];
    int tid = threadIdx.x, wid = tid >> 5, lane = tid & 31;
    int bm = blockIdx.y*128, bn = blockIdx.x*128;
    int wm = (wid & 3)*32;         // warp m-offset in tile
    int wn = (wid >> 2)*64;        // warp n-offset in tile

    uint32_t dbase = smem_u32(dsm);
    uint32_t pad = (1024u - (dbase & 1023u)) & 1023u;
    char* tp = dsm + pad;
    uint32_t tb = dbase + pad;
    // tiles: Ahi(0) Alo(16K) Bhi(32K) Blo(48K), each 128 rows x 128 bytes, SW128
    uint32_t aoff[3] = { tb, tb, tb + 16384 };            // A tile per pass
    uint32_t boff[3] = { tb + 32768, tb + 49152, tb + 32768 };  // B tile per pass
    const __nv_bfloat16* gA[2] = { Ahi, Alo };
    const __nv_bfloat16* gB[2] = { Bhi, Blo };

    float acc[2][8][4];
    #pragma unroll
    for (int i = 0; i < 2; i++)
        #pragma unroll
        for (int j = 0; j < 8; j++)
            #pragma unroll
            for (int q = 0; q < 4; q++) acc[i][j][q] = 0.f;

    // precompute ldmatrix lane-address components
    int a_row = (lane & 15);                    // + wm + mh*16
    int a_kc  = (lane >= 16) ? 8 : 0;           // + ks*16
    int b_n   = (lane & 7) + ((lane & 16) ? 8 : 0);   // + wn + q*16
    int b_kc  = (lane & 8) ? 8 : 0;             // + ks*16

    for (int c = 0; c < 75; ++c) {
        int c0 = c*64;
        // load 4 tiles (A hi/lo rows bm.., B hi/lo rows bn..)
        #pragma unroll
        for (int half = 0; half < 2; ++half) {     // 0: A, 1: B
            const __nv_bfloat16* src0 = half ? gB[0] : gA[0];
            const __nv_bfloat16* src1 = half ? gB[1] : gA[1];
            int grow0 = half ? bn : bm;
            char* d0 = tp + half*32768;
            char* d1 = d0 + 16384;
            #pragma unroll
            for (int it = 0; it < 4; ++it) {
                int idx = it*256 + tid;            // 1024 chunks of 16B
                int row = idx >> 3;
                int q   = idx & 7;
                uint32_t sw = sw128(row*128 + q*16);
                size_t g = (size_t)(grow0 + row)*DIN + c0 + q*8;
                *(uint4*)(d0 + sw) = *(const uint4*)(src0 + g);
                *(uint4*)(d1 + sw) = *(const uint4*)(src1 + g);
            }
        }
        __syncthreads();
        #pragma unroll
        for (int p = 0; p < 3; ++p) {
            uint32_t aT = aoff[p], bT = boff[p];
            #pragma unroll
            for (int ks = 0; ks < 4; ++ks) {
                uint32_t af[2][4];
                #pragma unroll
                for (int mh = 0; mh < 2; ++mh) {
                    int row = wm + mh*16 + a_row;
                    int kc = ks*16 + a_kc;
                    ldsm_x4(af[mh], aT + sw128(row*128 + kc*2));
                }
                uint32_t bf[4][4];
                #pragma unroll
                for (int q = 0; q < 4; ++q) {
                    int n = wn + q*16 + b_n;
                    int kc = ks*16 + b_kc;
                    ldsm_x4(bf[q], bT + sw128(n*128 + kc*2));
                }
                #pragma unroll
                for (int mh = 0; mh < 2; ++mh)
                    #pragma unroll
                    for (int q = 0; q < 4; ++q) {
                        mma16816(acc[mh][2*q],   af[mh], &bf[q][0]);
                        mma16816(acc[mh][2*q+1], af[mh], &bf[q][2]);
                    }
            }
        }
        __syncthreads();
    }

    // epilogue
    #pragma unroll
    for (int mh = 0; mh < 2; ++mh) {
        int row = bm + wm + mh*16 + (lane >> 2);
        #pragma unroll
        for (int nb = 0; nb < 8; ++nb) {
            int col = bn + wn + nb*8 + (lane & 3)*2;
            float* cp = C + (size_t)row*G1 + col;
            float b0 = bias[col], b1 = bias[col+1];
            cp[0] = acc[mh][nb][0] + b0;
            cp[1] = acc[mh][nb][1] + b1;
            float* cp2 = cp + 8*G1;
            cp2[0] = acc[mh][nb][2] + b0;
            cp2[1] = acc[mh][nb][3] + b1;
        }
    }
}

// ---------------- generic SIMT NT GEMM (small GEMMs) ----------------
__global__ void gemm_nt_bias(const float* __restrict__ A, const float* __restrict__ Bm,
                             const float* __restrict__ bias, float* __restrict__ C,
                             int M, int N, int K, int lda, int ldb, int ldc) {
    __shared__ float As[16][132];
    __shared__ float Bs[16][132];
    const int tid = threadIdx.x;
    const int tx = tid & 15, ty = tid >> 4;
    const int bm = blockIdx.y * 128, bn = blockIdx.x * 128;
    float acc[8][8];
    #pragma unroll
    for (int i = 0; i < 8; i++)
        #pragma unroll
        for (int j = 0; j < 8; j++) acc[i][j] = 0.f;
    for (int k0 = 0; k0 < K; k0 += 16) {
        #pragma unroll
        for (int q = 0; q < 2; q++) {
            int idx = tid + q*256;
            int row = idx >> 2;
            int c4  = (idx & 3) << 2;
            int gk = k0 + c4;
            float4 va = make_float4(0.f,0.f,0.f,0.f);
            float4 vb = make_float4(0.f,0.f,0.f,0.f);
            int ga = bm + row, gb = bn + row;
            if (ga < M && gk < K) {
                const float* p = A + (size_t)ga*lda;
                if (gk + 3 < K) va = *(const float4*)(p + gk);
                else {
                    va.x = p[gk];
                    if (gk+1 < K) va.y = p[gk+1];
                    if (gk+2 < K) va.z = p[gk+2];
                }
            }
            if (gb < N && gk < K) {
                const float* p = Bm + (size_t)gb*ldb;
                if (gk + 3 < K) vb = *(const float4*)(p + gk);
                else {
                    vb.x = p[gk];
                    if (gk+1 < K) vb.y = p[gk+1];
                    if (gk+2 < K) vb.z = p[gk+2];
                }
            }
            As[c4+0][row]=va.x; As[c4+1][row]=va.y; As[c4+2][row]=va.z; As[c4+3][row]=va.w;
            Bs[c4+0][row]=vb.x; Bs[c4+1][row]=vb.y; Bs[c4+2][row]=vb.z; Bs[c4+3][row]=vb.w;
        }
        __syncthreads();
        #pragma unroll
        for (int kk = 0; kk < 16; kk++) {
            float4 a0 = *(const float4*)&As[kk][ty*4];
            float4 a1 = *(const float4*)&As[kk][64 + ty*4];
            float4 b0 = *(const float4*)&Bs[kk][tx*4];
            float4 b1 = *(const float4*)&Bs[kk][64 + tx*4];
            float a[8] = {a0.x,a0.y,a0.z,a0.w,a1.x,a1.y,a1.z,a1.w};
            float b[8] = {b0.x,b0.y,b0.z,b0.w,b1.x,b1.y,b1.z,b1.w};
            #pragma unroll
            for (int i = 0; i < 8; i++)
                #pragma unroll
                for (int j = 0; j < 8; j++) acc[i][j] += a[i]*b[j];
        }
        __syncthreads();
    }
    #pragma unroll
    for (int i = 0; i < 8; i++) {
        int gm = bm + ((i < 4) ? ty*4+i : 64+ty*4+(i-4));
        if (gm >= M) continue;
        #pragma unroll
        for (int j = 0; j < 8; j++) {
            int gn = bn + ((j < 4) ? tx*4+j : 64+tx*4+(j-4));
            if (gn < N) C[(size_t)gm*ldc + gn] = acc[i][j] + bias[gn];
        }
    }
}

// ---------------- persistent GRU1: all 100 steps, one kernel ----------------
__global__ void __launch_bounds__(128) gru1_persist(
    const float* __restrict__ xi1, const float* __restrict__ Wh1,
    const float* __restrict__ bh1, float* __restrict__ h0, float* __restrict__ h1) {
    extern __shared__ float sm[];
    float* ws = sm;                  // [4 warps][3 gates][512]
    float* hs = sm + 4*3*HID1;       // [32][516]
    const int STR = 516;
    int tid = threadIdx.x, w = tid >> 5, l = tid & 31, blk = blockIdx.x;
    int j = blk*4 + w;

    for (int g = 0; g < 3; ++g) {
        const float* src = Wh1 + ((size_t)(g*HID1 + j))*HID1;
        for (int k = l*4; k < HID1; k += 128)
            *(float4*)&ws[(w*3+g)*HID1 + k] = *(const float4*)(src + k);
    }
    float br = bh1[j], bz = bh1[HID1+j], bnn = bh1[2*HID1+j];
    __syncthreads();

    float* hb[2] = { h0, h1 };
    for (int t = 0; t < TT; ++t) {
        const float* hin = hb[t & 1];
        float* hout = hb[(t+1) & 1];
        for (int i = tid; i < BB*(HID1/4); i += 128) {
            int b = i >> 7, k4 = (i & 127) << 2;
            float4 v = __ldcg((const float4*)(hin + b*HID1 + k4));
            *(float4*)&hs[b*STR + k4] = v;
        }
        __syncthreads();
        const float* wr = &ws[(w*3+0)*HID1];
        const float* wz = &ws[(w*3+1)*HID1];
        const float* wn = &ws[(w*3+2)*HID1];
        const float* hp = &hs[l*STR];
        float ar = 0.f, az = 0.f, an = 0.f;
        #pragma unroll 8
        for (int k = 0; k < HID1; k += 4) {
            float4 h4 = *(const float4*)(hp + k);
            float4 r4 = *(const float4*)(wr + k);
            float4 z4 = *(const float4*)(wz + k);
            float4 n4 = *(const float4*)(wn + k);
            ar += r4.x*h4.x + r4.y*h4.y + r4.z*h4.z + r4.w*h4.w;
            az += z4.x*h4.x + z4.y*h4.y + z4.z*h4.z + z4.w*h4.w;
            an += n4.x*h4.x + n4.y*h4.y + n4.z*h4.z + n4.w*h4.w;
        }
        const float* xrow = xi1 + ((size_t)(l*TT + t))*G1;
        float r = 1.f/(1.f + expf(-(xrow[j] + ar + br)));
        float z = 1.f/(1.f + expf(-(xrow[HID1+j] + az + bz)));
        float n = tanhf(xrow[2*HID1+j] + r*(an + bnn));
        float hn = (1.f - z)*n + z*hp[j];
        __stcg(hout + l*HID1 + j, hn);
        __threadfence();
        __syncthreads();
        if (tid == 0) g_flags[blk] = t + 1;
        while (g_flags[tid] < t + 1) { }
        __threadfence();
        __syncthreads();
    }
}

// ---------------- small helpers ----------------
__global__ void k_hrep(const float* __restrict__ hend, float* __restrict__ hrep) {
    int i = blockIdx.x*blockDim.x + threadIdx.x;
    if (i >= ROWS*HID1) return;
    int row = i >> 9;
    int d = i & 511;
    int b = row / TT, t = row - b*TT;
    hrep[i] = hend[b*HID1 + (t*HID1 + d)/TT];
}
__global__ void k_transpose450(const float* __restrict__ Wh2, float* __restrict__ Wh2T) {
    int i = blockIdx.x*blockDim.x + threadIdx.x;
    if (i >= G2*RHID2) return;
    int r = i / RHID2, c = i - r*RHID2;
    Wh2T[c*G2 + r] = Wh2[i];
}
__global__ void k_padWfc(const float* __restrict__ Wfc, float* __restrict__ WfcP) {
    int i = blockIdx.x*blockDim.x + threadIdx.x;
    if (i >= NN*DECS) return;
    int r = i / DECS, c = i - r*DECS;
    WfcP[i] = (c < RHID2) ? Wfc[r*RHID2 + c] : 0.f;
}
__global__ void k_init(float* __restrict__ h0) {
    int i = blockIdx.x*blockDim.x + threadIdx.x;
    if (i < BB*HID1) h0[i] = 0.f;
    if (i < 128) g_flags[i] = 0;
}

// ---------------- GRU2 ----------------
__global__ void k_gru2(const float* __restrict__ xi2, const float* __restrict__ Wh2T,
                       const float* __restrict__ bh2, float* __restrict__ dec) {
    __shared__ float h[RHID2];
    int b = blockIdx.x, tid = threadIdx.x;
    for (int i = tid; i < RHID2; i += blockDim.x) h[i] = 0.f;
    __syncthreads();
    for (int t = 0; t < TT; t++) {
        float ar = 0.f, az = 0.f, an = 0.f;
        if (tid < RHID2) {
            #pragma unroll 5
            for (int k = 0; k < RHID2; k++) {
                float hk = h[k];
                const float* wrow = Wh2T + k*G2;
                ar += wrow[tid]          * hk;
                az += wrow[RHID2 + tid]  * hk;
                an += wrow[2*RHID2 + tid]* hk;
            }
        }
        __syncthreads();
        if (tid < RHID2) {
            int row = b*TT + t;
            const float* xrow = xi2 + (size_t)row*G2;
            float r = 1.f/(1.f + expf(-(xrow[tid] + ar + bh2[tid])));
            float z = 1.f/(1.f + expf(-(xrow[RHID2+tid] + az + bh2[RHID2+tid])));
            float n = tanhf(xrow[2*RHID2+tid] + r*(an + bh2[2*RHID2+tid]));
            float hn = (1.f - z)*n + z*h[tid];
            h[tid] = hn;
            dec[(size_t)row*DECS + tid] = hn;
        }
        __syncthreads();
    }
}

// ---------------- launch ----------------
extern "C" void kernel_launch(void* const* d_in, const int* in_sizes, int n_in,
                              void* d_out, int out_size) {
    const float* window = (const float*)d_in[0];
    const float* emb    = (const float*)d_in[1];
    const float* w_init = (const float*)d_in[2];
    const float* w_root = (const float*)d_in[3];
    const float* arma_b = (const float*)d_in[4];
    const float* Wi1    = (const float*)d_in[5];
    const float* Wh1    = (const float*)d_in[6];
    const float* bi1    = (const float*)d_in[7];
    const float* bh1    = (const float*)d_in[8];
    const float* Wi2    = (const float*)d_in[9];
    const float* Wh2    = (const float*)d_in[10];
    const float* bi2    = (const float*)d_in[11];
    const float* bh2    = (const float*)d_in[12];
    const float* W_fc   = (const float*)d_in[13];
    const float* b_fc   = (const float*)d_in[14];
    float* out = (float*)d_out;

    float *Mt, *xf, *xi1, *hbase, *hrep, *xi2, *dec, *Wh2T, *WfcP;
    __nv_bfloat16 *Ahi, *Alo, *Bhi, *Blo;
    cudaGetSymbolAddress((void**)&Mt,    g_Mt);
    cudaGetSymbolAddress((void**)&xf,    g_xf);
    cudaGetSymbolAddress((void**)&Ahi,   g_Ahi);
    cudaGetSymbolAddress((void**)&Alo,   g_Alo);
    cudaGetSymbolAddress((void**)&Bhi,   g_Bhi);
    cudaGetSymbolAddress((void**)&Blo,   g_Blo);
    cudaGetSymbolAddress((void**)&xi1,   g_xi1);
    cudaGetSymbolAddress((void**)&hbase, g_h);
    cudaGetSymbolAddress((void**)&hrep,  g_hrep);
    cudaGetSymbolAddress((void**)&xi2,   g_xi2);
    cudaGetSymbolAddress((void**)&dec,   g_dec);
    cudaGetSymbolAddress((void**)&Wh2T,  g_Wh2T);
    cudaGetSymbolAddress((void**)&WfcP,  g_WfcP);
    float* hb0 = hbase;
    float* hb1 = hbase + BB*HID1;

    const int smem_gemm = 66560;                     // 64KB tiles + 1KB align pad
    const int smem_gru1 = (4*3*HID1 + BB*516) * 4;   // 90624 B
    cudaFuncSetAttribute(gemm_mma, cudaFuncAttributeMaxDynamicSharedMemorySize, smem_gemm);
    cudaFuncSetAttribute(gru1_persist, cudaFuncAttributeMaxDynamicSharedMemorySize, smem_gru1);

    k_graph<<<1, 256>>>(emb, Mt);
    k_perm<<<(NTOT + 255)/256, 256>>>(window, xf);
    k_convW<<<(int)(((size_t)G1*DIN + 255)/256), 256>>>(Wi1, Bhi, Blo);
    k_arma<<<ROWS, 160>>>(xf, emb, w_init, w_root, arma_b, Mt, Ahi, Alo);

    // big GEMM on HMMA tensor cores (bf16 hi/lo split, fp32 accumulate)
    gemm_mma<<<dim3(G1/128, ROWS/128), 256, smem_gemm>>>(Ahi, Alo, Bhi, Blo, bi1, xi1);

    k_init<<<(BB*HID1 + 255)/256, 256>>>(hb0);
    gru1_persist<<<128, 128, smem_gru1>>>(xi1, Wh1, bh1, hb0, hb1);
    // T=100 even -> final h in hb0

    k_hrep<<<(ROWS*HID1 + 255)/256, 256>>>(hb0, hrep);
    gemm_nt_bias<<<dim3((G2+127)/128, (ROWS+127)/128), 256>>>(hrep, Wi2, bi2, xi2,
                                                              ROWS, G2, HID1, HID1, HID1, G2);

    k_transpose450<<<(G2*RHID2 + 255)/256, 256>>>(Wh2, Wh2T);
    k_gru2<<<BB, 160>>>(xi2, Wh2T, bh2, dec);

    k_padWfc<<<(NN*DECS + 255)/256, 256>>>(W_fc, WfcP);
    gemm_nt_bias<<<dim3((NN+127)/128, (ROWS+127)/128), 256>>>(dec, WfcP, b_fc, out,
                                                              ROWS, NN, RHID2, DECS, DECS, NN);
}